// round 7
// baseline (speedup 1.0000x reference)
#include <cuda_runtime.h>
#include <cuda_bf16.h>

#define N_NODES 50000
#define N_EDGES 800000
#define NODE_IN 256
#define EDGE_IN 64
#define HID 128
#define OUT_DIM 16
#define EPS 1e-5f

#define N_PAD 50176   // 196 * 256

// Scratch (static device globals — no runtime allocation)
__device__ float g_hv[(size_t)N_NODES * HID];   // LN(GELU(node@Wn)) * exp(b_edge)
__device__ float g_h [(size_t)N_NODES * HID];   // segment-sum accumulator
__device__ uint4 g_WnF[16 * 16 * 32];           // pre-split W_node fragments (128 KB)
__device__ float g_P[HID], g_Q[HID];            // g_node*exp(b_edge), b_node*exp(b_edge)
// counting-sort scratch
__device__ int g_cnt [N_PAD];
__device__ int g_off [N_PAD];
__device__ int g_pos [N_PAD];
__device__ int g_bsum[256];
__device__ int g_boff[256];
__device__ int g_perm[N_EDGES];

__device__ __forceinline__ float gelu_exact(float x) {
    return 0.5f * x * (1.0f + erff(x * 0.7071067811865476f));
}

__device__ __forceinline__ void red_add_v4(float* p, float a, float b, float c, float d) {
    asm volatile("red.global.add.v4.f32 [%0], {%1,%2,%3,%4};"
                 :: "l"(p), "f"(a), "f"(b), "f"(c), "f"(d) : "memory");
}

__device__ __forceinline__ unsigned pack_bf2(float x, float y) {
    __nv_bfloat162 t = __floats2bfloat162_rn(x, y);
    return *reinterpret_cast<unsigned*>(&t);
}

__device__ __forceinline__ void split2(float2 v, unsigned& hi, unsigned& lo) {
    float hx = __bfloat162float(__float2bfloat16_rn(v.x));
    float hy = __bfloat162float(__float2bfloat16_rn(v.y));
    hi = pack_bf2(hx, hy);
    lo = pack_bf2(v.x - hx, v.y - hy);
}

__device__ __forceinline__ void mma_bf16(float d[4],
                                         unsigned a0, unsigned a1, unsigned a2, unsigned a3,
                                         unsigned b0, unsigned b1) {
    asm volatile(
        "mma.sync.aligned.m16n8k16.row.col.f32.bf16.bf16.f32 "
        "{%0,%1,%2,%3}, {%4,%5,%6,%7}, {%8,%9}, {%0,%1,%2,%3};"
        : "+f"(d[0]), "+f"(d[1]), "+f"(d[2]), "+f"(d[3])
        : "r"(a0), "r"(a1), "r"(a2), "r"(a3), "r"(b0), "r"(b1));
}

// ---------------------------------------------------------------------------
// Kernel 0: prep — split W_node fragments, fold exp(b_edge), zero histogram.
// ---------------------------------------------------------------------------
__global__ __launch_bounds__(256) void prep_kernel(
    const float* __restrict__ Wn, const float* __restrict__ gn,
    const float* __restrict__ bn, const float* __restrict__ be)
{
    const int i = blockIdx.x * 256 + threadIdx.x;   // 0..8191
    const int lane = i & 31, n = (i >> 5) & 15, ks = i >> 9;
    const int k0 = 16 * ks + 2 * (lane & 3);
    const int c  = 8 * n + (lane >> 2);
    const float v00 = Wn[(k0+0)*HID + c], v01 = Wn[(k0+1)*HID + c];
    const float v10 = Wn[(k0+8)*HID + c], v11 = Wn[(k0+9)*HID + c];
    unsigned h0, l0, h1, l1;
    split2(make_float2(v00, v01), h0, l0);
    split2(make_float2(v10, v11), h1, l1);
    g_WnF[i] = make_uint4(h0, h1, l0, l1);
    if (i < HID) {
        const float e = __expf(be[i]);
        g_P[i] = gn[i] * e;
        g_Q[i] = bn[i] * e;
    }
    for (int j = i; j < N_PAD; j += 8192) g_cnt[j] = 0;
}

// ---------------------------------------------------------------------------
// Counting sort of edges by dst: histogram, 2-level exclusive scan, scatter.
// ---------------------------------------------------------------------------
__global__ __launch_bounds__(256) void hist_kernel(const int* __restrict__ dst) {
    const int e = blockIdx.x * 256 + threadIdx.x;
    if (e < N_EDGES) atomicAdd(&g_cnt[dst[e]], 1);
}

__global__ __launch_bounds__(256) void scan1_kernel() {
    __shared__ int s[256];
    const int t = threadIdx.x, i = blockIdx.x * 256 + t;
    const int v = g_cnt[i];
    s[t] = v;
    #pragma unroll
    for (int off = 1; off < 256; off <<= 1) {
        __syncthreads();
        const int add = (t >= off) ? s[t - off] : 0;
        __syncthreads();
        s[t] += add;
    }
    g_off[i] = s[t] - v;                    // exclusive
    if (t == 255) g_bsum[blockIdx.x] = s[255];
}

__global__ __launch_bounds__(256) void scan2_kernel() {
    __shared__ int s[256];
    const int t = threadIdx.x;
    const int v = (t < 196) ? g_bsum[t] : 0;
    s[t] = v;
    #pragma unroll
    for (int off = 1; off < 256; off <<= 1) {
        __syncthreads();
        const int add = (t >= off) ? s[t - off] : 0;
        __syncthreads();
        s[t] += add;
    }
    g_boff[t] = s[t] - v;
}

__global__ __launch_bounds__(256) void scan3_kernel() {
    const int i = blockIdx.x * 256 + threadIdx.x;
    g_pos[i] = g_off[i] + g_boff[i >> 8];
}

__global__ __launch_bounds__(256) void scatter_kernel(const int* __restrict__ dst) {
    const int e = blockIdx.x * 256 + threadIdx.x;
    if (e < N_EDGES) {
        const int p = atomicAdd(&g_pos[dst[e]], 1);
        g_perm[p] = e;
    }
}

// ---------------------------------------------------------------------------
// Kernel 1: hv = (LN(GELU(nf @ Wn)) scaled by exp(b_edge)), MMA split-3.
// Also zeroes each tile's g_h rows (nodes without edges need zeros).
// ---------------------------------------------------------------------------
__global__ __launch_bounds__(384) void node_proj_kernel(const float* __restrict__ nf)
{
    extern __shared__ uint4 sBn[];   // 128 KB

    const int tid = threadIdx.x;
    for (int i = tid; i < 8192; i += 384) sBn[i] = g_WnF[i];
    __syncthreads();

    const int w = tid >> 5, lane = tid & 31;
    const int gid = lane >> 2, tig = lane & 3;
    const int nwarp = gridDim.x * 12;
    const float2* nf2 = (const float2*)nf;

    for (int t = blockIdx.x * 12 + w; t < N_NODES / 16; t += nwarp) {
        const int n0 = t * 16;

        {
            float4* hz = (float4*)(g_h + (size_t)n0 * HID);
            const float4 z4 = make_float4(0.f, 0.f, 0.f, 0.f);
            #pragma unroll
            for (int i = 0; i < 16; i++) hz[i * 32 + lane] = z4;
        }

        float d[16][4];
        #pragma unroll
        for (int n = 0; n < 16; n++) { d[n][0]=0.f; d[n][1]=0.f; d[n][2]=0.f; d[n][3]=0.f; }

        const size_t r0 = (size_t)(n0 + gid) * (NODE_IN/2);
        const size_t r1 = (size_t)(n0 + gid + 8) * (NODE_IN/2);
        #pragma unroll 4
        for (int ks = 0; ks < 16; ks++) {
            const float2 f0 = nf2[r0 + 8*ks + tig    ];
            const float2 f1 = nf2[r1 + 8*ks + tig    ];
            const float2 f2 = nf2[r0 + 8*ks + tig + 4];
            const float2 f3 = nf2[r1 + 8*ks + tig + 4];
            unsigned ah0, al0, ah1, al1, ah2, al2, ah3, al3;
            split2(f0, ah0, al0); split2(f1, ah1, al1);
            split2(f2, ah2, al2); split2(f3, ah3, al3);

            const uint4* Bk = &sBn[ks * 512 + lane];
            #pragma unroll
            for (int n = 0; n < 16; n++) {
                const uint4 bb = Bk[n * 32];
                mma_bf16(d[n], ah0, ah1, ah2, ah3, bb.x, bb.y);
                mma_bf16(d[n], ah0, ah1, ah2, ah3, bb.z, bb.w);
                mma_bf16(d[n], al0, al1, al2, al3, bb.x, bb.y);
            }
        }

        #pragma unroll
        for (int n = 0; n < 16; n++) {
            d[n][0] = gelu_exact(d[n][0]); d[n][1] = gelu_exact(d[n][1]);
            d[n][2] = gelu_exact(d[n][2]); d[n][3] = gelu_exact(d[n][3]);
        }

        float s0 = 0.f, q0 = 0.f, s1 = 0.f, q1 = 0.f;
        #pragma unroll
        for (int n = 0; n < 16; n++) {
            s0 += d[n][0] + d[n][1];
            q0 += d[n][0]*d[n][0] + d[n][1]*d[n][1];
            s1 += d[n][2] + d[n][3];
            q1 += d[n][2]*d[n][2] + d[n][3]*d[n][3];
        }
        s0 += __shfl_xor_sync(0xffffffffu, s0, 1); s0 += __shfl_xor_sync(0xffffffffu, s0, 2);
        q0 += __shfl_xor_sync(0xffffffffu, q0, 1); q0 += __shfl_xor_sync(0xffffffffu, q0, 2);
        s1 += __shfl_xor_sync(0xffffffffu, s1, 1); s1 += __shfl_xor_sync(0xffffffffu, s1, 2);
        q1 += __shfl_xor_sync(0xffffffffu, q1, 1); q1 += __shfl_xor_sync(0xffffffffu, q1, 2);
        const float mu0   = s0 * (1.f / HID);
        const float rstd0 = rsqrtf(q0 * (1.f / HID) - mu0*mu0 + EPS);
        const float mu1   = s1 * (1.f / HID);
        const float rstd1 = rsqrtf(q1 * (1.f / HID) - mu1*mu1 + EPS);

        float* o0 = g_hv + (size_t)(n0 + gid    ) * HID;
        float* o1 = g_hv + (size_t)(n0 + gid + 8) * HID;
        #pragma unroll
        for (int n = 0; n < 16; n++) {
            const int c0 = 8*n + 2*tig;
            const float2 P2 = *(const float2*)(g_P + c0);
            const float2 Q2 = *(const float2*)(g_Q + c0);
            *(float2*)(o0 + c0) = make_float2(
                (d[n][0]-mu0)*rstd0*P2.x + Q2.x, (d[n][1]-mu0)*rstd0*P2.y + Q2.y);
            *(float2*)(o1 + c0) = make_float2(
                (d[n][2]-mu1)*rstd1*P2.x + Q2.x, (d[n][3]-mu1)*rstd1*P2.y + Q2.y);
        }
    }
}

// ---------------------------------------------------------------------------
// Kernel 2 (hot): edges processed in dst-sorted order (via g_perm).
// MMA mainloop unchanged; epilogue transposed through smem:
//   lane = 4 contiguous cols; coalesced hv gather; running float4 accumulator
//   flushed with one coalesced red.v4 per distinct dst.
// ---------------------------------------------------------------------------
#define ZROW 132   // padded row stride (floats) for the z-tile

__global__ __launch_bounds__(128, 3) void edge_kernel(
    const float* __restrict__ ef, const int* __restrict__ src,
    const int* __restrict__ dst,  const float* __restrict__ We,
    const float* __restrict__ g)
{
    __shared__ uint4 sB[4 * 16 * 32];        // 32 KB  pre-split W_edge fragments
    __shared__ float sZ[4][16 * ZROW];       // 33 KB  z-tiles (per warp)
    __shared__ int   sIdx[4][32];            // [0..15]=src row, [16..31]=dst row
    __shared__ float2 sStat[4][16];          // mu, rstd per row

    const int tid = threadIdx.x;
    for (int i = tid; i < 2048; i += 128) {
        const int lane = i & 31, n = (i >> 5) & 15, ks = i >> 9;
        const int k0 = 16*ks + 2*(lane & 3);
        const int c  = 8*n + (lane >> 2);
        const float v00 = We[(k0+0)*HID + c], v01 = We[(k0+1)*HID + c];
        const float v10 = We[(k0+8)*HID + c], v11 = We[(k0+9)*HID + c];
        unsigned h0, l0, h1, l1;
        split2(make_float2(v00, v01), h0, l0);
        split2(make_float2(v10, v11), h1, l1);
        sB[i] = make_uint4(h0, h1, l0, l1);
    }
    __syncthreads();

    const int w = tid >> 5, lane = tid & 31;
    const int gid = lane >> 2, tig = lane & 3;
    const float4 ge4 = *(const float4*)(g + 4*lane);   // cols 4*lane..+3

    const float2* ef2 = (const float2*)ef;
    float* sZw = sZ[w];
    const int nTiles = N_EDGES / 16;      // 50000, exact
    const int nwarp  = gridDim.x * 4;

    for (int t = blockIdx.x * 4 + w; t < nTiles; t += nwarp) {
        const int e0 = t * 16;

        // permuted edge ids for this lane's two rows
        const int p0 = __ldg(&g_perm[e0 + gid]);
        const int p1 = __ldg(&g_perm[e0 + gid + 8]);
        const int sv0 = __ldg(&src[p0]), dv0 = __ldg(&dst[p0]);
        const int sv1 = __ldg(&src[p1]), dv1 = __ldg(&dst[p1]);

        float d[16][4];
        #pragma unroll
        for (int n = 0; n < 16; n++) { d[n][0]=0.f; d[n][1]=0.f; d[n][2]=0.f; d[n][3]=0.f; }

        const size_t ra = (size_t)p0 * 32;
        const size_t rb = (size_t)p1 * 32;
        #pragma unroll
        for (int ks = 0; ks < 4; ks++) {
            const float2 f0 = ef2[ra + 8*ks + tig    ];
            const float2 f1 = ef2[rb + 8*ks + tig    ];
            const float2 f2 = ef2[ra + 8*ks + tig + 4];
            const float2 f3 = ef2[rb + 8*ks + tig + 4];
            unsigned ah0, al0, ah1, al1, ah2, al2, ah3, al3;
            split2(f0, ah0, al0); split2(f1, ah1, al1);
            split2(f2, ah2, al2); split2(f3, ah3, al3);

            const uint4* sBk = &sB[ks * 512 + lane];
            #pragma unroll
            for (int n = 0; n < 16; n++) {
                const uint4 bb = sBk[n * 32];
                mma_bf16(d[n], ah0, ah1, ah2, ah3, bb.x, bb.y);  // hi*hi
                mma_bf16(d[n], ah0, ah1, ah2, ah3, bb.z, bb.w);  // hi*lo
                mma_bf16(d[n], al0, al1, al2, al3, bb.x, bb.y);  // lo*hi
            }
        }

        // LN stats per edge row (quad-reduce)
        float s0 = 0.f, q0 = 0.f, s1 = 0.f, q1 = 0.f;
        #pragma unroll
        for (int n = 0; n < 16; n++) {
            s0 += d[n][0] + d[n][1];
            q0 += d[n][0]*d[n][0] + d[n][1]*d[n][1];
            s1 += d[n][2] + d[n][3];
            q1 += d[n][2]*d[n][2] + d[n][3]*d[n][3];
        }
        s0 += __shfl_xor_sync(0xffffffffu, s0, 1); s0 += __shfl_xor_sync(0xffffffffu, s0, 2);
        q0 += __shfl_xor_sync(0xffffffffu, q0, 1); q0 += __shfl_xor_sync(0xffffffffu, q0, 2);
        s1 += __shfl_xor_sync(0xffffffffu, s1, 1); s1 += __shfl_xor_sync(0xffffffffu, s1, 2);
        q1 += __shfl_xor_sync(0xffffffffu, q1, 1); q1 += __shfl_xor_sync(0xffffffffu, q1, 2);

        const float mu0   = s0 * (1.f / HID);
        const float rstd0 = rsqrtf(q0 * (1.f / HID) - mu0*mu0 + EPS);
        const float mu1   = s1 * (1.f / HID);
        const float rstd1 = rsqrtf(q1 * (1.f / HID) - mu1*mu1 + EPS);

        // stage z-tile + per-row metadata in smem (transpose)
        __syncwarp();
        #pragma unroll
        for (int n = 0; n < 16; n++) {
            const int col = 8*n + 2*tig;
            *(float2*)&sZw[ gid      * ZROW + col] = make_float2(d[n][0], d[n][1]);
            *(float2*)&sZw[(gid + 8) * ZROW + col] = make_float2(d[n][2], d[n][3]);
        }
        if (tig == 0) {
            sStat[w][gid]     = make_float2(mu0, rstd0);
            sStat[w][gid + 8] = make_float2(mu1, rstd1);
            sIdx[w][gid]      = sv0;
            sIdx[w][gid + 8]  = sv1;
            sIdx[w][16 + gid] = dv0;
            sIdx[w][24 + gid] = dv1;
        }
        __syncwarp();

        // sequential per-edge phase: coalesced gather + dedup scatter
        float4 acc = make_float4(0.f, 0.f, 0.f, 0.f);
        int cur = sIdx[w][16];
        #pragma unroll
        for (int r = 0; r < 16; r++) {
            const float4 z  = *(const float4*)&sZw[r * ZROW + 4*lane];
            const float2 st = sStat[w][r];
            const int sv = sIdx[w][r];
            const int dv = sIdx[w][16 + r];
            const float4 hvv = ((const float4*)g_hv)[(size_t)sv * 32 + lane];
            const float m0 = hvv.x * __expf((z.x - st.x) * st.y * ge4.x);
            const float m1 = hvv.y * __expf((z.y - st.x) * st.y * ge4.y);
            const float m2 = hvv.z * __expf((z.z - st.x) * st.y * ge4.z);
            const float m3 = hvv.w * __expf((z.w - st.x) * st.y * ge4.w);
            if (dv != cur) {
                red_add_v4(g_h + (size_t)cur * HID + 4*lane, acc.x, acc.y, acc.z, acc.w);
                acc = make_float4(0.f, 0.f, 0.f, 0.f);
                cur = dv;
            }
            acc.x += m0; acc.y += m1; acc.z += m2; acc.w += m3;
        }
        red_add_v4(g_h + (size_t)cur * HID + 4*lane, acc.x, acc.y, acc.z, acc.w);
        __syncwarp();
    }
}

// ---------------------------------------------------------------------------
// Kernel 3: out = LayerNorm(GELU(h @ W_out))
// ---------------------------------------------------------------------------
__global__ __launch_bounds__(256) void out_kernel(
    const float* __restrict__ Wo, const float* __restrict__ g,
    const float* __restrict__ b,  float* __restrict__ out)
{
    __shared__ float sH [16 * HID];
    __shared__ float sWo[HID * OUT_DIM];

    const int tid = threadIdx.x;
    const int n0  = blockIdx.x * 16;
    {
        const float4* hv4 = (const float4*)(g_h + (size_t)n0 * HID);
        float4* sH4 = (float4*)sH;
        #pragma unroll
        for (int i = tid; i < 512; i += 256) sH4[i] = hv4[i];
        const float4* wv4 = (const float4*)Wo;
        float4* sW4 = (float4*)sWo;
        #pragma unroll
        for (int i = tid; i < 512; i += 256) sW4[i] = wv4[i];
    }
    __syncthreads();

    const int n = tid >> 4, c = tid & 15;
    float acc = 0.f;
    const float4* sHn = (const float4*)(sH + n * HID);
    #pragma unroll 4
    for (int k4 = 0; k4 < HID / 4; k4++) {
        const float4 a = sHn[k4];
        acc += a.x * sWo[(4*k4+0)*OUT_DIM + c];
        acc += a.y * sWo[(4*k4+1)*OUT_DIM + c];
        acc += a.z * sWo[(4*k4+2)*OUT_DIM + c];
        acc += a.w * sWo[(4*k4+3)*OUT_DIM + c];
    }

    const float v = gelu_exact(acc);
    float s = v, s2 = v * v;
    #pragma unroll
    for (int off = 8; off; off >>= 1) {
        s  += __shfl_xor_sync(0xffffffffu, s,  off);
        s2 += __shfl_xor_sync(0xffffffffu, s2, off);
    }
    const float mu   = s * (1.f / OUT_DIM);
    const float rstd = rsqrtf(s2 * (1.f / OUT_DIM) - mu * mu + EPS);
    out[(size_t)(n0 + n) * OUT_DIM + c] = (v - mu) * rstd * g[c] + b[c];
}

// ---------------------------------------------------------------------------
extern "C" void kernel_launch(void* const* d_in, const int* in_sizes, int n_in,
                              void* d_out, int out_size) {
    const float* node_feats = (const float*)d_in[0];
    const float* edge_feats = (const float*)d_in[1];
    const int*   src        = (const int*)  d_in[2];
    const int*   dst        = (const int*)  d_in[3];
    const float* W_node     = (const float*)d_in[4];
    const float* g_node     = (const float*)d_in[5];
    const float* b_node     = (const float*)d_in[6];
    const float* W_edge     = (const float*)d_in[7];
    const float* g_edge     = (const float*)d_in[8];
    const float* b_edge     = (const float*)d_in[9];
    const float* W_out      = (const float*)d_in[10];
    const float* g_out      = (const float*)d_in[11];
    const float* b_out      = (const float*)d_in[12];
    float* out = (float*)d_out;

    static bool attr_set = false;
    if (!attr_set) {
        cudaFuncSetAttribute(node_proj_kernel,
                             cudaFuncAttributeMaxDynamicSharedMemorySize, 131072);
        attr_set = true;
    }

    prep_kernel<<<32, 256>>>(W_node, g_node, b_node, b_edge);
    hist_kernel<<<3125, 256>>>(dst);
    scan1_kernel<<<196, 256>>>();
    scan2_kernel<<<1, 256>>>();
    scan3_kernel<<<196, 256>>>();
    scatter_kernel<<<3125, 256>>>(dst);
    node_proj_kernel<<<148, 384, 131072>>>(node_feats);
    edge_kernel<<<444, 128>>>(edge_feats, src, dst, W_edge, g_edge);
    out_kernel<<<N_NODES / 16, 256>>>(W_out, g_out, b_out, out);
}